// round 7
// baseline (speedup 1.0000x reference)
#include <cuda_runtime.h>
#include <cuda_bf16.h>
#include <math.h>

// Problem constants
#define NX   2048
#define NY   2048
#define DIM  28
#define TS   64   // 64x64 output tile per block, 256 threads, 4x4 per thread

// Bitplane signatures, 5 words per row:
//   plane 0..2 : value bits 0..2   (28 positions -> bits [0,28))
//   plane 3    : class bit 0  (v <= 2)
//   plane 4    : class bit 1  (v == 7)
// Per pair:  vd = OR of value-plane XORs (bit set iff values differ)
//            cd = OR of class-plane XORs (bit set iff classes differ; cd ⊆ vd)
//            dist_sum = popc(vd) + popc(cd)  in [0,56]
__global__ __launch_bounds__(256, 4) void fused_kernel(const int* __restrict__ set_r,
                                                       const int* __restrict__ set_t,
                                                       const float* __restrict__ sigma_ptr,
                                                       float* __restrict__ out)
{
    __shared__ unsigned int rsh[5][TS];   // plane-major
    __shared__ unsigned int tsh[5][TS];
    __shared__ float lut[57];

    const int tid = threadIdx.x;
    const int i0 = blockIdx.y * TS;
    const int j0 = blockIdx.x * TS;

    // ---- pack phase: threads 0..63 pack r rows, 64..127 pack t rows ----
    if (tid < 128) {
        const int row = tid & 63;
        const bool is_r = (tid < 64);
        const int* src = is_r ? (set_r + (size_t)(i0 + row) * DIM)
                              : (set_t + (size_t)(j0 + row) * DIM);

        uint4 raw[7];
        const uint4* s4 = (const uint4*)src;
#pragma unroll
        for (int k = 0; k < 7; k++) raw[k] = s4[k];
        const int* v = (const int*)raw;

        unsigned int b0 = 0, b1 = 0, b2 = 0, c0 = 0, c1 = 0;
#pragma unroll
        for (int p = 0; p < DIM; p++) {
            unsigned int vv = (unsigned int)v[p];
            b0 |= (vv & 1u) << p;
            b1 |= ((vv >> 1) & 1u) << p;
            b2 |= ((vv >> 2) & 1u) << p;
            c0 |= (unsigned int)(vv <= 2u) << p;
            c1 |= (unsigned int)(vv == 7u) << p;
        }
        if (is_r) {
            rsh[0][row] = b0; rsh[1][row] = b1; rsh[2][row] = b2;
            rsh[3][row] = c0; rsh[4][row] = c1;
        } else {
            tsh[0][row] = b0; tsh[1][row] = b1; tsh[2][row] = b2;
            tsh[3][row] = c0; tsh[4][row] = c1;
        }
    } else if (tid - 128 < 57) {
        const int s = tid - 128;
        float sig = *sigma_ptr;
        float d = (float)s * (1.0f / 28.0f);
        lut[s] = expf(-d * d / (2.0f * sig * sig));
    }
    __syncthreads();

    // ---- compute phase: 16x16 threads, 4x4 outputs per thread,
    //      all operands loaded as uint4 (LDS.128) ----
    const int tx = tid & 15;
    const int ty = tid >> 4;
    const int jb = tx << 2;
    const int ib = ty << 2;

    uint4 tq[5];   // component c = t-column jb+c, per plane
    uint4 aq[5];   // component r = a-row ib+r, per plane
#pragma unroll
    for (int p = 0; p < 5; p++) {
        tq[p] = *(const uint4*)&tsh[p][jb];
        aq[p] = *(const uint4*)&rsh[p][ib];
    }

#pragma unroll
    for (int r = 0; r < 4; r++) {
        const unsigned int a0 = ((const unsigned int*)&aq[0])[r];
        const unsigned int a1 = ((const unsigned int*)&aq[1])[r];
        const unsigned int a2 = ((const unsigned int*)&aq[2])[r];
        const unsigned int a3 = ((const unsigned int*)&aq[3])[r];
        const unsigned int a4 = ((const unsigned int*)&aq[4])[r];

        float o[4];
#pragma unroll
        for (int c = 0; c < 4; c++) {
            unsigned int vd = (a0 ^ ((const unsigned int*)&tq[0])[c])
                            | (a1 ^ ((const unsigned int*)&tq[1])[c])
                            | (a2 ^ ((const unsigned int*)&tq[2])[c]);
            unsigned int cd = (a3 ^ ((const unsigned int*)&tq[3])[c])
                            | (a4 ^ ((const unsigned int*)&tq[4])[c]);
            int s = __popc(vd) + __popc(cd);
            o[c] = lut[s];
        }
        float4 q = make_float4(o[0], o[1], o[2], o[3]);
        *(float4*)(out + (size_t)(i0 + ib + r) * NY + j0 + jb) = q;
    }
}

extern "C" void kernel_launch(void* const* d_in, const int* in_sizes, int n_in,
                              void* d_out, int out_size)
{
    const int*   set_r = (const int*)d_in[0];
    const int*   set_t = (const int*)d_in[1];
    const float* sigma = (const float*)d_in[2];
    float*       out   = (float*)d_out;

    dim3 grid(NY / TS, NX / TS);
    fused_kernel<<<grid, 256>>>(set_r, set_t, sigma, out);
}